// round 1
// baseline (speedup 1.0000x reference)
#include <cuda_runtime.h>

// Problem constants
#define B_  2
#define S_  2048
#define D_  1024
#define H_  16
#define DK_ 64
#define M_  (B_*S_)   // 4096 rows

// Scratch (device globals: allocation-free)
__device__ float g_q[4194304];    // [B,H,S,DK]
__device__ float g_k[4194304];
__device__ float g_v[4194304];
__device__ float g_attn[4194304]; // [B,S,D]

// ---------------------------------------------------------------------------
// GEMM: C[M,N] = A[M,K] @ W[K,N] + bias
// MODE 0: plain row-major write. MODE 1: write into [B,H,S,DK] head layout.
// BM=BN=128, BK=8, 256 threads, 8x8 per-thread micro-tile.
// ---------------------------------------------------------------------------
template<int MODE>
__global__ __launch_bounds__(256)
void gemm_bias(const float* __restrict__ A, const float* __restrict__ W,
               const float* __restrict__ bias, float* __restrict__ C,
               int Mdim, int Ndim, int Kdim)
{
    const int BM = 128, BN = 128, BK = 8;
    __shared__ float As[BK][BM];
    __shared__ float Ws[BK][BN];

    int t  = threadIdx.x;
    int bm = blockIdx.y * BM;
    int bn = blockIdx.x * BN;

    int arow = t >> 1;           // 0..127
    int acol = (t & 1) * 4;      // 0 or 4
    int wrow = t >> 5;           // 0..7
    int wcol = (t & 31) * 4;     // 0..124
    int ty   = t >> 4;           // 0..15
    int tx   = t & 15;           // 0..15

    float acc[8][8];
    #pragma unroll
    for (int i = 0; i < 8; i++)
        #pragma unroll
        for (int j = 0; j < 8; j++) acc[i][j] = 0.f;

    const float* Aptr = A + (size_t)(bm + arow) * Kdim + acol;
    const float* Wptr = W + (size_t)wrow * Ndim + bn + wcol;

    for (int k0 = 0; k0 < Kdim; k0 += BK) {
        float4 av = *(const float4*)(Aptr + k0);
        As[acol + 0][arow] = av.x;
        As[acol + 1][arow] = av.y;
        As[acol + 2][arow] = av.z;
        As[acol + 3][arow] = av.w;
        float4 wv = *(const float4*)(Wptr + (size_t)k0 * Ndim);
        *(float4*)&Ws[wrow][wcol] = wv;
        __syncthreads();

        #pragma unroll
        for (int kk = 0; kk < BK; kk++) {
            float af[8], wf[8];
            *(float4*)&af[0] = *(const float4*)&As[kk][ty * 8];
            *(float4*)&af[4] = *(const float4*)&As[kk][ty * 8 + 4];
            *(float4*)&wf[0] = *(const float4*)&Ws[kk][tx * 8];
            *(float4*)&wf[4] = *(const float4*)&Ws[kk][tx * 8 + 4];
            #pragma unroll
            for (int i = 0; i < 8; i++)
                #pragma unroll
                for (int j = 0; j < 8; j++)
                    acc[i][j] += af[i] * wf[j];
        }
        __syncthreads();
    }

    #pragma unroll
    for (int i = 0; i < 8; i++) {
        int row = bm + ty * 8 + i;
        if (MODE == 0) {
            int colbase = bn + tx * 8;
            #pragma unroll
            for (int j = 0; j < 8; j++)
                C[(size_t)row * Ndim + colbase + j] = acc[i][j] + bias[colbase + j];
        } else {
            // row = b*S + s; col = h*DK + dk -> [B,H,S,DK]
            int b = row >> 11;        // / 2048
            int s = row & 2047;
            int colbase = bn + tx * 8;            // 8-col span never crosses a head (DK=64)
            int h   = colbase >> 6;
            int dkb = colbase & 63;
            float* dst = C + (((size_t)(b * H_ + h) * S_ + s) * DK_ + dkb);
            #pragma unroll
            for (int j = 0; j < 8; j++)
                dst[j] = acc[i][j] + bias[colbase + j];
        }
    }
}

// ---------------------------------------------------------------------------
// Causal flash attention, fp32.
// One thread owns one query row (128 rows/CTA). K/V tiles of 64 rows in smem.
// q pre-scaled by 1/sqrt(DK). Online softmax with 16-wide chunks.
// ---------------------------------------------------------------------------
__global__ __launch_bounds__(128)
void flash_attn(const float* __restrict__ qh, const float* __restrict__ kh,
                const float* __restrict__ vh, float* __restrict__ out)
{
    const int FM = 128, FN = 64;
    __shared__ float Ksh[FN][DK_];
    __shared__ float Vsh[FN][DK_];

    int bh = blockIdx.y;            // b*H + h
    int b  = bh >> 4;
    int h  = bh & 15;
    int m0 = blockIdx.x * FM;
    int t  = threadIdx.x;
    int qi = m0 + t;                // global query index within (b,h)

    float q[DK_];
    const float4* qr = (const float4*)(qh + ((size_t)bh * S_ + qi) * DK_);
    #pragma unroll
    for (int d4 = 0; d4 < 16; d4++) {
        float4 v = qr[d4];
        q[4*d4+0] = v.x * 0.125f;   // 1/sqrt(64)
        q[4*d4+1] = v.y * 0.125f;
        q[4*d4+2] = v.z * 0.125f;
        q[4*d4+3] = v.w * 0.125f;
    }

    float o[DK_];
    #pragma unroll
    for (int d = 0; d < DK_; d++) o[d] = 0.f;
    float mx = -1e30f, l = 0.f;

    const float* kbase = kh + (size_t)bh * S_ * DK_;
    const float* vbase = vh + (size_t)bh * S_ * DK_;

    int kend = m0 + FM;             // causal: only keys < m0+FM matter for this CTA
    for (int kb = 0; kb < kend; kb += FN) {
        // cooperative tile load: 64x64 floats each for K and V (8 float4/thread)
        for (int idx = t; idx < FN * DK_ / 4; idx += FM) {
            int r = idx >> 4, c = idx & 15;
            ((float4*)Ksh)[idx] = ((const float4*)(kbase + (size_t)(kb + r) * DK_))[c];
            ((float4*)Vsh)[idx] = ((const float4*)(vbase + (size_t)(kb + r) * DK_))[c];
        }
        __syncthreads();

        int jmax = qi - kb;         // valid keys: j <= jmax
        #pragma unroll 1
        for (int jc = 0; jc < FN; jc += 16) {
            float sreg[16];
            #pragma unroll
            for (int jj = 0; jj < 16; jj++) {
                int j = jc + jj;
                const float4* kr = (const float4*)&Ksh[j][0];
                float s0 = 0.f, s1 = 0.f, s2 = 0.f, s3 = 0.f;
                #pragma unroll
                for (int d4 = 0; d4 < 16; d4++) {
                    float4 kv = kr[d4];
                    s0 += q[4*d4+0] * kv.x;
                    s1 += q[4*d4+1] * kv.y;
                    s2 += q[4*d4+2] * kv.z;
                    s3 += q[4*d4+3] * kv.w;
                }
                float s = (s0 + s1) + (s2 + s3);
                sreg[jj] = (j <= jmax) ? s : -1e30f;
            }
            float cmax = sreg[0];
            #pragma unroll
            for (int jj = 1; jj < 16; jj++) cmax = fmaxf(cmax, sreg[jj]);
            if (cmax > mx) {
                float alpha = __expf(mx - cmax);
                l *= alpha;
                #pragma unroll
                for (int d = 0; d < DK_; d++) o[d] *= alpha;
                mx = cmax;
            }
            #pragma unroll
            for (int jj = 0; jj < 16; jj++) {
                float p = __expf(sreg[jj] - mx);
                l += p;
                const float4* vr = (const float4*)&Vsh[jc + jj][0];
                #pragma unroll
                for (int d4 = 0; d4 < 16; d4++) {
                    float4 vv = vr[d4];
                    o[4*d4+0] += p * vv.x;
                    o[4*d4+1] += p * vv.y;
                    o[4*d4+2] += p * vv.z;
                    o[4*d4+3] += p * vv.w;
                }
            }
        }
        __syncthreads();
    }

    float inv = 1.f / l;
    float4* orow = (float4*)(out + ((size_t)b * S_ + qi) * D_ + h * DK_);
    #pragma unroll
    for (int d4 = 0; d4 < 16; d4++) {
        float4 v;
        v.x = o[4*d4+0] * inv;
        v.y = o[4*d4+1] * inv;
        v.z = o[4*d4+2] * inv;
        v.w = o[4*d4+3] * inv;
        orow[d4] = v;
    }
}

// ---------------------------------------------------------------------------
// Launch: 3 projection GEMMs -> flash attention -> output GEMM
// ---------------------------------------------------------------------------
extern "C" void kernel_launch(void* const* d_in, const int* in_sizes, int n_in,
                              void* d_out, int out_size)
{
    const float* Q   = (const float*)d_in[0];
    const float* K   = (const float*)d_in[1];
    const float* V   = (const float*)d_in[2];
    const float* W_q = (const float*)d_in[3];
    const float* b_q = (const float*)d_in[4];
    const float* W_k = (const float*)d_in[5];
    const float* b_k = (const float*)d_in[6];
    const float* W_v = (const float*)d_in[7];
    const float* b_v = (const float*)d_in[8];
    const float* W_o = (const float*)d_in[9];
    const float* b_o = (const float*)d_in[10];
    // d_in[11] is the causal mask; causality is hardcoded in flash_attn.
    float* out = (float*)d_out;

    float *gq, *gk, *gv, *ga;
    cudaGetSymbolAddress((void**)&gq, g_q);
    cudaGetSymbolAddress((void**)&gk, g_k);
    cudaGetSymbolAddress((void**)&gv, g_v);
    cudaGetSymbolAddress((void**)&ga, g_attn);

    dim3 gemm_grid(D_ / 128, M_ / 128);      // (8, 32)
    gemm_bias<1><<<gemm_grid, 256>>>(Q, W_q, b_q, gq, M_, D_, D_);
    gemm_bias<1><<<gemm_grid, 256>>>(K, W_k, b_k, gk, M_, D_, D_);
    gemm_bias<1><<<gemm_grid, 256>>>(V, W_v, b_v, gv, M_, D_, D_);

    flash_attn<<<dim3(S_ / 128, B_ * H_), 128>>>(gq, gk, gv, ga);

    gemm_bias<0><<<gemm_grid, 256>>>(ga, W_o, b_o, out, M_, D_, D_);
}

// round 3
// speedup vs baseline: 2.1141x; 2.1141x over previous
#include <cuda_runtime.h>

// Problem constants
#define B_  2
#define S_  2048
#define D_  1024
#define H_  16
#define DK_ 64
#define M_  (B_*S_)   // 4096 rows

// Scratch (device globals: allocation-free)
__device__ float g_q[4194304];    // [B,H,S,DK]
__device__ float g_k[4194304];
__device__ float g_v[4194304];
__device__ float g_attn[4194304]; // [B,S,D]

// ---------------------------------------------------------------------------
// tf32 helpers
// ---------------------------------------------------------------------------
__device__ __forceinline__ unsigned f2tf32(float x) {
    unsigned r;
    asm("cvt.rna.tf32.f32 %0, %1;" : "=r"(r) : "f"(x));
    return r;
}

__device__ __forceinline__ void mma_tf32(float c[4], const unsigned a[4], const unsigned b[2]) {
    asm volatile(
        "mma.sync.aligned.m16n8k8.row.col.f32.tf32.tf32.f32 "
        "{%0,%1,%2,%3}, {%4,%5,%6,%7}, {%8,%9}, {%0,%1,%2,%3};"
        : "+f"(c[0]), "+f"(c[1]), "+f"(c[2]), "+f"(c[3])
        : "r"(a[0]), "r"(a[1]), "r"(a[2]), "r"(a[3]),
          "r"(b[0]), "r"(b[1]));
}

// ---------------------------------------------------------------------------
// tf32 tensor-core GEMM: C[M,N] = A[M,K] @ W[K,N] + bias
// MODE 0: row-major write. MODE 1: write into [B,H,S,DK] head layout.
// BM=BN=128, BK=16, 256 threads (8 warps, 4x2), warp tile 32x64,
// mma m16n8k8, double-buffered smem.
// ---------------------------------------------------------------------------
#define BKp 132   // padded row stride in floats (2-way max conflicts)

template<int MODE>
__global__ __launch_bounds__(256)
void gemm_tf32(const float* __restrict__ A, const float* __restrict__ W,
               const float* __restrict__ bias, float* __restrict__ C,
               int Mdim, int Ndim, int Kdim)
{
    const int BM = 128, BN = 128, BK = 16;
    __shared__ unsigned As[2][BK][BKp];   // [k][m] (A transposed into smem)
    __shared__ unsigned Bs[2][BK][BKp];   // [k][n]

    int t    = threadIdx.x;
    int lane = t & 31;
    int warp = t >> 5;
    int gid  = lane >> 2;   // 0..7
    int tid4 = lane & 3;    // 0..3

    int bm = blockIdx.y * BM;
    int bn = blockIdx.x * BN;
    int wm = (warp & 3) * 32;   // warp m-offset in tile
    int wn = (warp >> 2) * 64;  // warp n-offset in tile

    // Global-load mapping
    // A tile: 128 rows x 16 k. thread -> row = t&127, kq = (t>>7)*8 ; 2 float4
    int a_row = t & 127;
    int a_k   = (t >> 7) * 8;
    // B tile: 16 k-rows x 128 n. thread -> k = t>>4, n0 = (t&15)*8 ; 2 float4
    int b_k  = t >> 4;
    int b_n  = (t & 15) * 8;

    const float* Aptr = A + (size_t)(bm + a_row) * Kdim + a_k;
    const float* Wptr = W + (size_t)b_k * Ndim + bn + b_n;

    float acc[2][8][4];
    #pragma unroll
    for (int mt = 0; mt < 2; mt++)
        #pragma unroll
        for (int nt = 0; nt < 8; nt++)
            #pragma unroll
            for (int i = 0; i < 4; i++) acc[mt][nt][i] = 0.f;

    float4 ar0, ar1, br0, br1;

    // prologue: load tile 0
    ar0 = *(const float4*)(Aptr);
    ar1 = *(const float4*)(Aptr + 4);
    br0 = *(const float4*)(Wptr);
    br1 = *(const float4*)(Wptr + 4);
    {
        As[0][a_k+0][a_row] = f2tf32(ar0.x);
        As[0][a_k+1][a_row] = f2tf32(ar0.y);
        As[0][a_k+2][a_row] = f2tf32(ar0.z);
        As[0][a_k+3][a_row] = f2tf32(ar0.w);
        As[0][a_k+4][a_row] = f2tf32(ar1.x);
        As[0][a_k+5][a_row] = f2tf32(ar1.y);
        As[0][a_k+6][a_row] = f2tf32(ar1.z);
        As[0][a_k+7][a_row] = f2tf32(ar1.w);
        Bs[0][b_k][b_n+0] = f2tf32(br0.x);
        Bs[0][b_k][b_n+1] = f2tf32(br0.y);
        Bs[0][b_k][b_n+2] = f2tf32(br0.z);
        Bs[0][b_k][b_n+3] = f2tf32(br0.w);
        Bs[0][b_k][b_n+4] = f2tf32(br1.x);
        Bs[0][b_k][b_n+5] = f2tf32(br1.y);
        Bs[0][b_k][b_n+6] = f2tf32(br1.z);
        Bs[0][b_k][b_n+7] = f2tf32(br1.w);
    }
    __syncthreads();

    int cur = 0;
    for (int k0 = 0; k0 < Kdim; k0 += BK) {
        bool has_next = (k0 + BK) < Kdim;
        if (has_next) {
            const float* Ap = Aptr + (k0 + BK);
            const float* Wp = Wptr + (size_t)(k0 + BK) * Ndim;
            ar0 = *(const float4*)(Ap);
            ar1 = *(const float4*)(Ap + 4);
            br0 = *(const float4*)(Wp);
            br1 = *(const float4*)(Wp + 4);
        }

        // compute on buf cur: 2 k8 steps
        #pragma unroll
        for (int s = 0; s < 2; s++) {
            int kb = s * 8;
            unsigned afr[2][4], bfr[8][2];
            #pragma unroll
            for (int mt = 0; mt < 2; mt++) {
                int m0 = wm + mt * 16 + gid;
                afr[mt][0] = As[cur][kb + tid4    ][m0    ];
                afr[mt][1] = As[cur][kb + tid4    ][m0 + 8];
                afr[mt][2] = As[cur][kb + tid4 + 4][m0    ];
                afr[mt][3] = As[cur][kb + tid4 + 4][m0 + 8];
            }
            #pragma unroll
            for (int nt = 0; nt < 8; nt++) {
                int n0 = wn + nt * 8 + gid;
                bfr[nt][0] = Bs[cur][kb + tid4    ][n0];
                bfr[nt][1] = Bs[cur][kb + tid4 + 4][n0];
            }
            #pragma unroll
            for (int mt = 0; mt < 2; mt++)
                #pragma unroll
                for (int nt = 0; nt < 8; nt++)
                    mma_tf32(acc[mt][nt], afr[mt], bfr[nt]);
        }

        if (has_next) {
            int nb = cur ^ 1;
            As[nb][a_k+0][a_row] = f2tf32(ar0.x);
            As[nb][a_k+1][a_row] = f2tf32(ar0.y);
            As[nb][a_k+2][a_row] = f2tf32(ar0.z);
            As[nb][a_k+3][a_row] = f2tf32(ar0.w);
            As[nb][a_k+4][a_row] = f2tf32(ar1.x);
            As[nb][a_k+5][a_row] = f2tf32(ar1.y);
            As[nb][a_k+6][a_row] = f2tf32(ar1.z);
            As[nb][a_k+7][a_row] = f2tf32(ar1.w);
            Bs[nb][b_k][b_n+0] = f2tf32(br0.x);
            Bs[nb][b_k][b_n+1] = f2tf32(br0.y);
            Bs[nb][b_k][b_n+2] = f2tf32(br0.z);
            Bs[nb][b_k][b_n+3] = f2tf32(br0.w);
            Bs[nb][b_k][b_n+4] = f2tf32(br1.x);
            Bs[nb][b_k][b_n+5] = f2tf32(br1.y);
            Bs[nb][b_k][b_n+6] = f2tf32(br1.z);
            Bs[nb][b_k][b_n+7] = f2tf32(br1.w);
            __syncthreads();
            cur = nb;
        }
    }

    // Epilogue
    #pragma unroll
    for (int mt = 0; mt < 2; mt++) {
        int r0 = bm + wm + mt * 16 + gid;
        #pragma unroll
        for (int nt = 0; nt < 8; nt++) {
            int col = bn + wn + nt * 8 + tid4 * 2;
            float bv0 = bias[col], bv1 = bias[col + 1];
            if (MODE == 0) {
                float* p0 = C + (size_t)r0 * Ndim + col;
                float* p1 = C + (size_t)(r0 + 8) * Ndim + col;
                p0[0] = acc[mt][nt][0] + bv0;
                p0[1] = acc[mt][nt][1] + bv1;
                p1[0] = acc[mt][nt][2] + bv0;
                p1[1] = acc[mt][nt][3] + bv1;
            } else {
                int h  = col >> 6;
                int dk = col & 63;
                int b0r = r0 >> 11, s0r = r0 & 2047;
                int b1r = (r0 + 8) >> 11, s1r = (r0 + 8) & 2047;
                float* p0 = C + (((size_t)(b0r * H_ + h) * S_ + s0r) * DK_ + dk);
                float* p1 = C + (((size_t)(b1r * H_ + h) * S_ + s1r) * DK_ + dk);
                p0[0] = acc[mt][nt][0] + bv0;
                p0[1] = acc[mt][nt][1] + bv1;
                p1[0] = acc[mt][nt][2] + bv0;
                p1[1] = acc[mt][nt][3] + bv1;
            }
        }
    }
}

// ---------------------------------------------------------------------------
// Causal flash attention, fp32 (unchanged from R1).
// ---------------------------------------------------------------------------
__global__ __launch_bounds__(128)
void flash_attn(const float* __restrict__ qh, const float* __restrict__ kh,
                const float* __restrict__ vh, float* __restrict__ out)
{
    const int FM = 128, FN = 64;
    __shared__ float Ksh[FN][DK_];
    __shared__ float Vsh[FN][DK_];

    int bh = blockIdx.y;            // b*H + h
    int b  = bh >> 4;
    int h  = bh & 15;
    int m0 = blockIdx.x * FM;
    int t  = threadIdx.x;
    int qi = m0 + t;                // global query index within (b,h)

    float q[DK_];
    const float4* qr = (const float4*)(qh + ((size_t)bh * S_ + qi) * DK_);
    #pragma unroll
    for (int d4 = 0; d4 < 16; d4++) {
        float4 v = qr[d4];
        q[4*d4+0] = v.x * 0.125f;   // 1/sqrt(64)
        q[4*d4+1] = v.y * 0.125f;
        q[4*d4+2] = v.z * 0.125f;
        q[4*d4+3] = v.w * 0.125f;
    }

    float o[DK_];
    #pragma unroll
    for (int d = 0; d < DK_; d++) o[d] = 0.f;
    float mx = -1e30f, l = 0.f;

    const float* kbase = kh + (size_t)bh * S_ * DK_;
    const float* vbase = vh + (size_t)bh * S_ * DK_;

    int kend = m0 + FM;             // causal
    for (int kb = 0; kb < kend; kb += FN) {
        for (int idx = t; idx < FN * DK_ / 4; idx += FM) {
            int r = idx >> 4, c = idx & 15;
            ((float4*)Ksh)[idx] = ((const float4*)(kbase + (size_t)(kb + r) * DK_))[c];
            ((float4*)Vsh)[idx] = ((const float4*)(vbase + (size_t)(kb + r) * DK_))[c];
        }
        __syncthreads();

        int jmax = qi - kb;
        #pragma unroll 1
        for (int jc = 0; jc < FN; jc += 16) {
            float sreg[16];
            #pragma unroll
            for (int jj = 0; jj < 16; jj++) {
                int j = jc + jj;
                const float4* kr = (const float4*)&Ksh[j][0];
                float s0 = 0.f, s1 = 0.f, s2 = 0.f, s3 = 0.f;
                #pragma unroll
                for (int d4 = 0; d4 < 16; d4++) {
                    float4 kv = kr[d4];
                    s0 += q[4*d4+0] * kv.x;
                    s1 += q[4*d4+1] * kv.y;
                    s2 += q[4*d4+2] * kv.z;
                    s3 += q[4*d4+3] * kv.w;
                }
                float s = (s0 + s1) + (s2 + s3);
                sreg[jj] = (j <= jmax) ? s : -1e30f;
            }
            float cmax = sreg[0];
            #pragma unroll
            for (int jj = 1; jj < 16; jj++) cmax = fmaxf(cmax, sreg[jj]);
            if (cmax > mx) {
                float alpha = __expf(mx - cmax);
                l *= alpha;
                #pragma unroll
                for (int d = 0; d < DK_; d++) o[d] *= alpha;
                mx = cmax;
            }
            #pragma unroll
            for (int jj = 0; jj < 16; jj++) {
                float p = __expf(sreg[jj] - mx);
                l += p;
                const float4* vr = (const float4*)&Vsh[jc + jj][0];
                #pragma unroll
                for (int d4 = 0; d4 < 16; d4++) {
                    float4 vv = vr[d4];
                    o[4*d4+0] += p * vv.x;
                    o[4*d4+1] += p * vv.y;
                    o[4*d4+2] += p * vv.z;
                    o[4*d4+3] += p * vv.w;
                }
            }
        }
        __syncthreads();
    }

    float inv = 1.f / l;
    float4* orow = (float4*)(out + ((size_t)b * S_ + qi) * D_ + h * DK_);
    #pragma unroll
    for (int d4 = 0; d4 < 16; d4++) {
        float4 v;
        v.x = o[4*d4+0] * inv;
        v.y = o[4*d4+1] * inv;
        v.z = o[4*d4+2] * inv;
        v.w = o[4*d4+3] * inv;
        orow[d4] = v;
    }
}

// ---------------------------------------------------------------------------
// Launch: 3 projection GEMMs -> flash attention -> output GEMM
// ---------------------------------------------------------------------------
extern "C" void kernel_launch(void* const* d_in, const int* in_sizes, int n_in,
                              void* d_out, int out_size)
{
    const float* Q   = (const float*)d_in[0];
    const float* K   = (const float*)d_in[1];
    const float* V   = (const float*)d_in[2];
    const float* W_q = (const float*)d_in[3];
    const float* b_q = (const float*)d_in[4];
    const float* W_k = (const float*)d_in[5];
    const float* b_k = (const float*)d_in[6];
    const float* W_v = (const float*)d_in[7];
    const float* b_v = (const float*)d_in[8];
    const float* W_o = (const float*)d_in[9];
    const float* b_o = (const float*)d_in[10];
    float* out = (float*)d_out;

    float *gq, *gk, *gv, *ga;
    cudaGetSymbolAddress((void**)&gq, g_q);
    cudaGetSymbolAddress((void**)&gk, g_k);
    cudaGetSymbolAddress((void**)&gv, g_v);
    cudaGetSymbolAddress((void**)&ga, g_attn);

    dim3 gemm_grid(D_ / 128, M_ / 128);      // (8, 32)
    gemm_tf32<1><<<gemm_grid, 256>>>(Q, W_q, b_q, gq, M_, D_, D_);
    gemm_tf32<1><<<gemm_grid, 256>>>(K, W_k, b_k, gk, M_, D_, D_);
    gemm_tf32<1><<<gemm_grid, 256>>>(V, W_v, b_v, gv, M_, D_, D_);

    flash_attn<<<dim3(S_ / 128, B_ * H_), 128>>>(gq, gk, gv, ga);

    gemm_tf32<0><<<gemm_grid, 256>>>(ga, W_o, b_o, out, M_, D_, D_);
}

// round 8
// speedup vs baseline: 4.1173x; 1.9476x over previous
#include <cuda_runtime.h>
#include <cstdint>

// Problem constants
#define B_  2
#define S_  2048
#define D_  1024
#define H_  16
#define DK_ 64
#define M_  (B_*S_)   // 4096 rows

// Scratch (device globals: allocation-free)
__device__ float g_q[4194304];    // [B,H,S,DK]
__device__ float g_k[4194304];
__device__ float g_v[4194304];
__device__ float g_attn[4194304]; // [B,S,D]

// ---------------------------------------------------------------------------
// helpers
// ---------------------------------------------------------------------------
__device__ __forceinline__ unsigned f2tf32(float x) {
    unsigned r;
    asm("cvt.rna.tf32.f32 %0, %1;" : "=r"(r) : "f"(x));
    return r;
}

__device__ __forceinline__ void mma_tf32(float c[4], const unsigned a[4], const unsigned b[2]) {
    asm volatile(
        "mma.sync.aligned.m16n8k8.row.col.f32.tf32.tf32.f32 "
        "{%0,%1,%2,%3}, {%4,%5,%6,%7}, {%8,%9}, {%0,%1,%2,%3};"
        : "+f"(c[0]), "+f"(c[1]), "+f"(c[2]), "+f"(c[3])
        : "r"(a[0]), "r"(a[1]), "r"(a[2]), "r"(a[3]),
          "r"(b[0]), "r"(b[1]));
}

// Fast e^x on the FMA/ALU pipes (no MUFU). Handles very negative x (mask) -> ~0.
__device__ __forceinline__ float fexp(float x) {
    float y = x * 1.44269504089f;          // log2(e)
    y = fmaxf(y, -126.0f);
    float z = __fadd_rn(y, 12582912.0f);   // rint via magic number
    int   iz = __float_as_int(z);
    float k = __fadd_rn(z, -12582912.0f);
    float f = y - k;                       // f in [-0.5, 0.5]
    float u = f * 0.69314718056f;
    float p = fmaf(u, fmaf(u, fmaf(u, fmaf(u, 0.041666668f, 0.16666667f), 0.5f), 1.0f), 1.0f);
    return __int_as_float(__float_as_int(p) + (iz << 23));  // p * 2^k
}

// ---------------------------------------------------------------------------
// tf32 tensor-core GEMM (verbatim from R2, known good):
// C[M,N] = A[M,K] @ W[K,N] + bias
// MODE 0: row-major write. MODE 1: write into [B,H,S,DK] head layout.
// ---------------------------------------------------------------------------
#define BKp 132

template<int MODE>
__global__ __launch_bounds__(256)
void gemm_tf32(const float* __restrict__ A, const float* __restrict__ W,
               const float* __restrict__ bias, float* __restrict__ C,
               int Mdim, int Ndim, int Kdim)
{
    const int BM = 128, BN = 128, BK = 16;
    __shared__ unsigned As[2][BK][BKp];
    __shared__ unsigned Bs[2][BK][BKp];

    int t    = threadIdx.x;
    int lane = t & 31;
    int warp = t >> 5;
    int gid  = lane >> 2;
    int tid4 = lane & 3;

    int bm = blockIdx.y * BM;
    int bn = blockIdx.x * BN;
    int wm = (warp & 3) * 32;
    int wn = (warp >> 2) * 64;

    int a_row = t & 127;
    int a_k   = (t >> 7) * 8;
    int b_k  = t >> 4;
    int b_n  = (t & 15) * 8;

    const float* Aptr = A + (size_t)(bm + a_row) * Kdim + a_k;
    const float* Wptr = W + (size_t)b_k * Ndim + bn + b_n;

    float acc[2][8][4];
    #pragma unroll
    for (int mt = 0; mt < 2; mt++)
        #pragma unroll
        for (int nt = 0; nt < 8; nt++)
            #pragma unroll
            for (int i = 0; i < 4; i++) acc[mt][nt][i] = 0.f;

    float4 ar0, ar1, br0, br1;

    ar0 = *(const float4*)(Aptr);
    ar1 = *(const float4*)(Aptr + 4);
    br0 = *(const float4*)(Wptr);
    br1 = *(const float4*)(Wptr + 4);
    {
        As[0][a_k+0][a_row] = f2tf32(ar0.x);
        As[0][a_k+1][a_row] = f2tf32(ar0.y);
        As[0][a_k+2][a_row] = f2tf32(ar0.z);
        As[0][a_k+3][a_row] = f2tf32(ar0.w);
        As[0][a_k+4][a_row] = f2tf32(ar1.x);
        As[0][a_k+5][a_row] = f2tf32(ar1.y);
        As[0][a_k+6][a_row] = f2tf32(ar1.z);
        As[0][a_k+7][a_row] = f2tf32(ar1.w);
        Bs[0][b_k][b_n+0] = f2tf32(br0.x);
        Bs[0][b_k][b_n+1] = f2tf32(br0.y);
        Bs[0][b_k][b_n+2] = f2tf32(br0.z);
        Bs[0][b_k][b_n+3] = f2tf32(br0.w);
        Bs[0][b_k][b_n+4] = f2tf32(br1.x);
        Bs[0][b_k][b_n+5] = f2tf32(br1.y);
        Bs[0][b_k][b_n+6] = f2tf32(br1.z);
        Bs[0][b_k][b_n+7] = f2tf32(br1.w);
    }
    __syncthreads();

    int cur = 0;
    for (int k0 = 0; k0 < Kdim; k0 += BK) {
        bool has_next = (k0 + BK) < Kdim;
        if (has_next) {
            const float* Ap = Aptr + (k0 + BK);
            const float* Wp = Wptr + (size_t)(k0 + BK) * Ndim;
            ar0 = *(const float4*)(Ap);
            ar1 = *(const float4*)(Ap + 4);
            br0 = *(const float4*)(Wp);
            br1 = *(const float4*)(Wp + 4);
        }

        #pragma unroll
        for (int s = 0; s < 2; s++) {
            int kb = s * 8;
            unsigned afr[2][4], bfr[8][2];
            #pragma unroll
            for (int mt = 0; mt < 2; mt++) {
                int m0 = wm + mt * 16 + gid;
                afr[mt][0] = As[cur][kb + tid4    ][m0    ];
                afr[mt][1] = As[cur][kb + tid4    ][m0 + 8];
                afr[mt][2] = As[cur][kb + tid4 + 4][m0    ];
                afr[mt][3] = As[cur][kb + tid4 + 4][m0 + 8];
            }
            #pragma unroll
            for (int nt = 0; nt < 8; nt++) {
                int n0 = wn + nt * 8 + gid;
                bfr[nt][0] = Bs[cur][kb + tid4    ][n0];
                bfr[nt][1] = Bs[cur][kb + tid4 + 4][n0];
            }
            #pragma unroll
            for (int mt = 0; mt < 2; mt++)
                #pragma unroll
                for (int nt = 0; nt < 8; nt++)
                    mma_tf32(acc[mt][nt], afr[mt], bfr[nt]);
        }

        if (has_next) {
            int nb = cur ^ 1;
            As[nb][a_k+0][a_row] = f2tf32(ar0.x);
            As[nb][a_k+1][a_row] = f2tf32(ar0.y);
            As[nb][a_k+2][a_row] = f2tf32(ar0.z);
            As[nb][a_k+3][a_row] = f2tf32(ar0.w);
            As[nb][a_k+4][a_row] = f2tf32(ar1.x);
            As[nb][a_k+5][a_row] = f2tf32(ar1.y);
            As[nb][a_k+6][a_row] = f2tf32(ar1.z);
            As[nb][a_k+7][a_row] = f2tf32(ar1.w);
            Bs[nb][b_k][b_n+0] = f2tf32(br0.x);
            Bs[nb][b_k][b_n+1] = f2tf32(br0.y);
            Bs[nb][b_k][b_n+2] = f2tf32(br0.z);
            Bs[nb][b_k][b_n+3] = f2tf32(br0.w);
            Bs[nb][b_k][b_n+4] = f2tf32(br1.x);
            Bs[nb][b_k][b_n+5] = f2tf32(br1.y);
            Bs[nb][b_k][b_n+6] = f2tf32(br1.z);
            Bs[nb][b_k][b_n+7] = f2tf32(br1.w);
            __syncthreads();
            cur = nb;
        }
    }

    #pragma unroll
    for (int mt = 0; mt < 2; mt++) {
        int r0 = bm + wm + mt * 16 + gid;
        #pragma unroll
        for (int nt = 0; nt < 8; nt++) {
            int col = bn + wn + nt * 8 + tid4 * 2;
            float bv0 = bias[col], bv1 = bias[col + 1];
            if (MODE == 0) {
                float* p0 = C + (size_t)r0 * Ndim + col;
                float* p1 = C + (size_t)(r0 + 8) * Ndim + col;
                p0[0] = acc[mt][nt][0] + bv0;
                p0[1] = acc[mt][nt][1] + bv1;
                p1[0] = acc[mt][nt][2] + bv0;
                p1[1] = acc[mt][nt][3] + bv1;
            } else {
                int h  = col >> 6;
                int dk = col & 63;
                int b0r = r0 >> 11, s0r = r0 & 2047;
                int b1r = (r0 + 8) >> 11, s1r = (r0 + 8) & 2047;
                float* p0 = C + (((size_t)(b0r * H_ + h) * S_ + s0r) * DK_ + dk);
                float* p1 = C + (((size_t)(b1r * H_ + h) * S_ + s1r) * DK_ + dk);
                p0[0] = acc[mt][nt][0] + bv0;
                p0[1] = acc[mt][nt][1] + bv1;
                p1[0] = acc[mt][nt][2] + bv0;
                p1[1] = acc[mt][nt][3] + bv1;
            }
        }
    }
}

// ---------------------------------------------------------------------------
// Tensor-core causal flash attention (mma.sync tf32 + FFMA fast-exp).
// 256 threads / 8 warps. Q tile = 128 rows (m16 per warp), K/V tile = 64 keys.
// smem strides: K=68 (conflict-free K-frags), V=72 (conflict-free V-frags),
// P/Q per-warp tile stride 68 (conflict-free A-frags).
// ---------------------------------------------------------------------------
#define KST 68
#define VST 72
#define PST 68
#define FA_SMEM_U32 (64*KST + 64*VST + 8*16*PST)   // 17664 u32 = 70656 B

__global__ __launch_bounds__(256)
void flash_mma(const float* __restrict__ qh, const float* __restrict__ kh,
               const float* __restrict__ vh, float* __restrict__ out)
{
    extern __shared__ unsigned sm[];
    unsigned* Ksh = sm;                       // [64][KST]
    unsigned* Vsh = sm + 64*KST;              // [64][VST]
    int t = threadIdx.x;
    int wid = t >> 5, lane = t & 31;
    int g = lane >> 2, q = lane & 3;
    unsigned* Pw = sm + 64*KST + 64*VST + wid * 16 * PST;  // per-warp [16][PST]

    int bh = blockIdx.y;
    int b  = bh >> 4;
    int h  = bh & 15;
    int m0 = blockIdx.x * 128;
    int r0w = m0 + wid * 16;                  // warp's first query row

    const float* qbase = qh + (size_t)bh * S_ * DK_;
    const float* kbase = kh + (size_t)bh * S_ * DK_;
    const float* vbase = vh + (size_t)bh * S_ * DK_;

    // ---- stage this warp's Q tile (16x64, scaled, tf32) and load A-frags ----
    #pragma unroll
    for (int i = 0; i < 8; ++i) {
        int idx = lane + 32 * i;              // 0..255 float4s
        int row = idx >> 4, c4 = idx & 15;
        float4 v = *(const float4*)(qbase + (size_t)(r0w + row) * DK_ + c4 * 4);
        uint4 u;
        u.x = f2tf32(v.x * 0.125f); u.y = f2tf32(v.y * 0.125f);
        u.z = f2tf32(v.z * 0.125f); u.w = f2tf32(v.w * 0.125f);
        *(uint4*)(Pw + row * PST + c4 * 4) = u;
    }
    __syncwarp();

    unsigned aq[8][4];
    #pragma unroll
    for (int kk = 0; kk < 8; ++kk) {
        aq[kk][0] = Pw[ g      * PST + kk * 8 + q    ];
        aq[kk][1] = Pw[(g + 8) * PST + kk * 8 + q    ];
        aq[kk][2] = Pw[ g      * PST + kk * 8 + q + 4];
        aq[kk][3] = Pw[(g + 8) * PST + kk * 8 + q + 4];
    }

    float od[8][4];
    #pragma unroll
    for (int nt = 0; nt < 8; nt++)
        #pragma unroll
        for (int i = 0; i < 4; i++) od[nt][i] = 0.f;
    float mrow0 = -1e30f, mrow1 = -1e30f, lrow0 = 0.f, lrow1 = 0.f;

    int nkb = 2 * (blockIdx.x + 1);           // causal: key blocks 0..nkb-1

    for (int kb = 0; kb < nkb; ++kb) {
        int jb = kb * 64;
        __syncthreads();                      // prior iteration consumers done
        // ---- cooperative K/V tile fill (64x64 each, tf32) ----
        #pragma unroll
        for (int i = 0; i < 4; ++i) {
            int idx = t + 256 * i;            // 0..1023 float4s
            int row = idx >> 4, c4 = idx & 15;
            float4 kv = *(const float4*)(kbase + (size_t)(jb + row) * DK_ + c4 * 4);
            uint4 ku;
            ku.x = f2tf32(kv.x); ku.y = f2tf32(kv.y);
            ku.z = f2tf32(kv.z); ku.w = f2tf32(kv.w);
            *(uint4*)(Ksh + row * KST + c4 * 4) = ku;
            float4 vv = *(const float4*)(vbase + (size_t)(jb + row) * DK_ + c4 * 4);
            uint4 vu;
            vu.x = f2tf32(vv.x); vu.y = f2tf32(vv.y);
            vu.z = f2tf32(vv.z); vu.w = f2tf32(vv.w);
            *(uint4*)(Vsh + row * VST + c4 * 4) = vu;
        }
        __syncthreads();

        if (jb > r0w + 15) continue;          // fully-future block for this warp

        // ---- S = Q @ K^T (16 x 64), fp32 accum ----
        float s[8][4];
        #pragma unroll
        for (int nt = 0; nt < 8; nt++)
            #pragma unroll
            for (int i = 0; i < 4; i++) s[nt][i] = 0.f;

        #pragma unroll
        for (int kk = 0; kk < 8; ++kk) {
            #pragma unroll
            for (int nt = 0; nt < 8; ++nt) {
                unsigned bfr[2];
                bfr[0] = Ksh[(nt * 8 + g) * KST + kk * 8 + q    ];
                bfr[1] = Ksh[(nt * 8 + g) * KST + kk * 8 + q + 4];
                mma_tf32(s[nt], aq[kk], bfr);
            }
        }

        // ---- causal mask (diagonal blocks only) ----
        if (jb + 63 > r0w) {
            int row0 = r0w + g, row1 = r0w + g + 8;
            #pragma unroll
            for (int nt = 0; nt < 8; ++nt) {
                int j0 = jb + nt * 8 + 2 * q;
                if (j0     > row0) s[nt][0] = -1e30f;
                if (j0 + 1 > row0) s[nt][1] = -1e30f;
                if (j0     > row1) s[nt][2] = -1e30f;
                if (j0 + 1 > row1) s[nt][3] = -1e30f;
            }
        }

        // ---- online softmax ----
        float mx0 = s[0][0], mx1 = s[0][2];
        #pragma unroll
        for (int nt = 0; nt < 8; ++nt) {
            mx0 = fmaxf(mx0, fmaxf(s[nt][0], s[nt][1]));
            mx1 = fmaxf(mx1, fmaxf(s[nt][2], s[nt][3]));
        }
        mx0 = fmaxf(mx0, __shfl_xor_sync(0xffffffffu, mx0, 1));
        mx0 = fmaxf(mx0, __shfl_xor_sync(0xffffffffu, mx0, 2));
        mx1 = fmaxf(mx1, __shfl_xor_sync(0xffffffffu, mx1, 1));
        mx1 = fmaxf(mx1, __shfl_xor_sync(0xffffffffu, mx1, 2));

        float mn0 = fmaxf(mrow0, mx0);
        float mn1 = fmaxf(mrow1, mx1);
        float alpha0 = fexp(mrow0 - mn0);
        float alpha1 = fexp(mrow1 - mn1);
        mrow0 = mn0; mrow1 = mn1;

        float rs0 = 0.f, rs1 = 0.f;
        #pragma unroll
        for (int nt = 0; nt < 8; ++nt) {
            float p0 = fexp(s[nt][0] - mn0);
            float p1 = fexp(s[nt][1] - mn0);
            float p2 = fexp(s[nt][2] - mn1);
            float p3 = fexp(s[nt][3] - mn1);
            rs0 += p0 + p1;
            rs1 += p2 + p3;
            uint2 u01 = make_uint2(f2tf32(p0), f2tf32(p1));
            uint2 u23 = make_uint2(f2tf32(p2), f2tf32(p3));
            *(uint2*)(Pw + g       * PST + nt * 8 + 2 * q) = u01;
            *(uint2*)(Pw + (g + 8) * PST + nt * 8 + 2 * q) = u23;
        }
        rs0 += __shfl_xor_sync(0xffffffffu, rs0, 1);
        rs0 += __shfl_xor_sync(0xffffffffu, rs0, 2);
        rs1 += __shfl_xor_sync(0xffffffffu, rs1, 1);
        rs1 += __shfl_xor_sync(0xffffffffu, rs1, 2);
        lrow0 = lrow0 * alpha0 + rs0;
        lrow1 = lrow1 * alpha1 + rs1;

        #pragma unroll
        for (int nt = 0; nt < 8; ++nt) {
            od[nt][0] *= alpha0; od[nt][1] *= alpha0;
            od[nt][2] *= alpha1; od[nt][3] *= alpha1;
        }
        __syncwarp();

        // ---- O += P @ V (16 x 64) ----
        #pragma unroll
        for (int kk = 0; kk < 8; ++kk) {
            unsigned ap[4];
            ap[0] = Pw[ g      * PST + kk * 8 + q    ];
            ap[1] = Pw[(g + 8) * PST + kk * 8 + q    ];
            ap[2] = Pw[ g      * PST + kk * 8 + q + 4];
            ap[3] = Pw[(g + 8) * PST + kk * 8 + q + 4];
            #pragma unroll
            for (int nt = 0; nt < 8; ++nt) {
                unsigned bfr[2];
                bfr[0] = Vsh[(kk * 8 + q    ) * VST + nt * 8 + g];
                bfr[1] = Vsh[(kk * 8 + q + 4) * VST + nt * 8 + g];
                mma_tf32(od[nt], ap, bfr);
            }
        }
        __syncwarp();   // Pw reads done before next-iteration P store
    }

    // ---- epilogue: normalize + write [B,S,D] ----
    float inv0 = 1.f / lrow0;
    float inv1 = 1.f / lrow1;
    int row0 = m0 + wid * 16 + g;
    int row1 = row0 + 8;
    float* o0 = out + ((size_t)b * S_ + row0) * D_ + h * DK_;
    float* o1 = out + ((size_t)b * S_ + row1) * D_ + h * DK_;
    #pragma unroll
    for (int nt = 0; nt < 8; ++nt) {
        int col = nt * 8 + 2 * q;
        float2 v0 = make_float2(od[nt][0] * inv0, od[nt][1] * inv0);
        float2 v1 = make_float2(od[nt][2] * inv1, od[nt][3] * inv1);
        *(float2*)(o0 + col) = v0;
        *(float2*)(o1 + col) = v1;
    }
}

// ---------------------------------------------------------------------------
// Launch: 3 projection GEMMs -> mma flash attention -> output GEMM
// ---------------------------------------------------------------------------
extern "C" void kernel_launch(void* const* d_in, const int* in_sizes, int n_in,
                              void* d_out, int out_size)
{
    const float* Q   = (const float*)d_in[0];
    const float* K   = (const float*)d_in[1];
    const float* V   = (const float*)d_in[2];
    const float* W_q = (const float*)d_in[3];
    const float* b_q = (const float*)d_in[4];
    const float* W_k = (const float*)d_in[5];
    const float* b_k = (const float*)d_in[6];
    const float* W_v = (const float*)d_in[7];
    const float* b_v = (const float*)d_in[8];
    const float* W_o = (const float*)d_in[9];
    const float* b_o = (const float*)d_in[10];
    float* out = (float*)d_out;

    float *gq, *gk, *gv, *ga;
    cudaGetSymbolAddress((void**)&gq, g_q);
    cudaGetSymbolAddress((void**)&gk, g_k);
    cudaGetSymbolAddress((void**)&gv, g_v);
    cudaGetSymbolAddress((void**)&ga, g_attn);

    cudaFuncSetAttribute(flash_mma, cudaFuncAttributeMaxDynamicSharedMemorySize,
                         FA_SMEM_U32 * 4);

    dim3 gemm_grid(D_ / 128, M_ / 128);      // (8, 32)
    gemm_tf32<1><<<gemm_grid, 256>>>(Q, W_q, b_q, gq, M_, D_, D_);
    gemm_tf32<1><<<gemm_grid, 256>>>(K, W_k, b_k, gk, M_, D_, D_);
    gemm_tf32<1><<<gemm_grid, 256>>>(V, W_v, b_v, gv, M_, D_, D_);

    flash_mma<<<dim3(S_ / 128, B_ * H_), 256, FA_SMEM_U32 * 4>>>(gq, gk, gv, ga);

    gemm_tf32<0><<<gemm_grid, 256>>>(ga, W_o, b_o, out, M_, D_, D_);
}

// round 9
// speedup vs baseline: 7.3766x; 1.7916x over previous
#include <cuda_runtime.h>
#include <cuda_fp16.h>
#include <cstdint>

// Problem constants
#define B_  2
#define S_  2048
#define D_  1024
#define H_  16
#define DK_ 64
#define M_  (B_*S_)   // 4096 rows

// Scratch (device globals: allocation-free)
__device__ float g_q[4194304];    // [B,H,S,DK]
__device__ float g_k[4194304];
__device__ float g_v[4194304];
__device__ float g_attn[4194304]; // [B,S,D]

// ---------------------------------------------------------------------------
// helpers
// ---------------------------------------------------------------------------
__device__ __forceinline__ unsigned f2h2(float lo, float hi) {
    __half2 h = __floats2half2_rn(lo, hi);
    return *(unsigned*)&h;
}

__device__ __forceinline__ uint32_t smem_u32(const void* p) {
    uint32_t a;
    asm("{ .reg .u64 t; cvta.to.shared.u64 t, %1; cvt.u32.u64 %0, t; }" : "=r"(a) : "l"(p));
    return a;
}

// fp16 mma, fp32 accumulate: D(16x8) += A(16x16) @ B(16x8)
__device__ __forceinline__ void mma_f16(float c[4], const unsigned a[4], const unsigned b[2]) {
    asm volatile(
        "mma.sync.aligned.m16n8k16.row.col.f32.f16.f16.f32 "
        "{%0,%1,%2,%3}, {%4,%5,%6,%7}, {%8,%9}, {%0,%1,%2,%3};"
        : "+f"(c[0]), "+f"(c[1]), "+f"(c[2]), "+f"(c[3])
        : "r"(a[0]), "r"(a[1]), "r"(a[2]), "r"(a[3]),
          "r"(b[0]), "r"(b[1]));
}

// ldmatrix x2 transposed (b16): B-fragments for m16n8k16 from row-major [k][n] tile
__device__ __forceinline__ void ldsm_x2_t(unsigned& r0, unsigned& r1, uint32_t addr) {
    asm volatile("ldmatrix.sync.aligned.m8n8.x2.trans.shared.b16 {%0,%1}, [%2];"
                 : "=r"(r0), "=r"(r1) : "r"(addr));
}

// Fast e^x on the FMA/ALU pipes (no MUFU). Handles very negative x (mask) -> ~0.
__device__ __forceinline__ float fexp(float x) {
    float y = x * 1.44269504089f;          // log2(e)
    y = fmaxf(y, -126.0f);
    float z = __fadd_rn(y, 12582912.0f);   // rint via magic number
    int   iz = __float_as_int(z);
    float k = __fadd_rn(z, -12582912.0f);
    float f = y - k;                       // f in [-0.5, 0.5]
    float u = f * 0.69314718056f;
    float p = fmaf(u, fmaf(u, fmaf(u, fmaf(u, 0.041666668f, 0.16666667f), 0.5f), 1.0f), 1.0f);
    return __int_as_float(__float_as_int(p) + (iz << 23));  // p * 2^k
}

// ---------------------------------------------------------------------------
// fp16 tensor-core GEMM: C[M,N] = A[M,K] @ W[K,N] + bias  (fp32 accumulate)
// BM=BN=128, BK=32, 256 threads (8 warps, 4x2), warp tile 32x64, mma m16n8k16.
// smem: As/Bs in [k2][m]/[k2][n] half2 layout, row stride 136 (8 mod 32 ->
// conflict-free fragment LDS). Double buffered, register-staged globals.
// MODE 0: row-major write. MODE 1: write into [B,H,S,DK] head layout.
// ---------------------------------------------------------------------------
#define GST 136

template<int MODE>
__global__ __launch_bounds__(256)
void gemm_f16(const float* __restrict__ A, const float* __restrict__ W,
              const float* __restrict__ bias, float* __restrict__ C,
              int Mdim, int Ndim, int Kdim)
{
    __shared__ unsigned As[2][16][GST];   // [k2][m] half2 (k even=lo, odd=hi)
    __shared__ unsigned Bs[2][16][GST];   // [k2][n]

    int t    = threadIdx.x;
    int lane = t & 31;
    int warp = t >> 5;
    int g    = lane >> 2;   // 0..7
    int q    = lane & 3;    // 0..3

    int bm = blockIdx.y * 128;
    int bn = blockIdx.x * 128;
    int wm = (warp & 3) * 32;
    int wn = (warp >> 2) * 64;

    // A fill mapping: thread -> row m = t>>1, k-half (t&1)*16, 4x float4
    int am  = t >> 1;
    int ak  = (t & 1) * 16;
    int ak2 = (t & 1) * 8;
    // B fill mapping: thread -> k2 = t>>4 (k pair), n0 = (t&15)*8
    int bk2 = t >> 4;
    int bn0 = (t & 15) * 8;

    const float* Aptr = A + (size_t)(bm + am) * Kdim + ak;
    const float* W0   = W + (size_t)(2 * bk2) * Ndim + bn + bn0;

    float acc[2][8][4];
    #pragma unroll
    for (int mt = 0; mt < 2; mt++)
        #pragma unroll
        for (int nt = 0; nt < 8; nt++)
            #pragma unroll
            for (int i = 0; i < 4; i++) acc[mt][nt][i] = 0.f;

    float4 a0, a1, a2, a3, w00, w01, w10, w11;

    // prologue: load + store k-chunk 0
    a0 = *(const float4*)(Aptr);
    a1 = *(const float4*)(Aptr + 4);
    a2 = *(const float4*)(Aptr + 8);
    a3 = *(const float4*)(Aptr + 12);
    w00 = *(const float4*)(W0);
    w01 = *(const float4*)(W0 + 4);
    w10 = *(const float4*)(W0 + Ndim);
    w11 = *(const float4*)(W0 + Ndim + 4);
    {
        As[0][ak2 + 0][am] = f2h2(a0.x, a0.y);
        As[0][ak2 + 1][am] = f2h2(a0.z, a0.w);
        As[0][ak2 + 2][am] = f2h2(a1.x, a1.y);
        As[0][ak2 + 3][am] = f2h2(a1.z, a1.w);
        As[0][ak2 + 4][am] = f2h2(a2.x, a2.y);
        As[0][ak2 + 5][am] = f2h2(a2.z, a2.w);
        As[0][ak2 + 6][am] = f2h2(a3.x, a3.y);
        As[0][ak2 + 7][am] = f2h2(a3.z, a3.w);
        unsigned* bp = &Bs[0][bk2][bn0];
        bp[0] = f2h2(w00.x, w10.x); bp[1] = f2h2(w00.y, w10.y);
        bp[2] = f2h2(w00.z, w10.z); bp[3] = f2h2(w00.w, w10.w);
        bp[4] = f2h2(w01.x, w11.x); bp[5] = f2h2(w01.y, w11.y);
        bp[6] = f2h2(w01.z, w11.z); bp[7] = f2h2(w01.w, w11.w);
    }
    __syncthreads();

    int cur = 0;
    for (int k0 = 0; k0 < Kdim; k0 += 32) {
        bool has_next = (k0 + 32) < Kdim;
        if (has_next) {
            const float* Ap = Aptr + (k0 + 32);
            a0 = *(const float4*)(Ap);
            a1 = *(const float4*)(Ap + 4);
            a2 = *(const float4*)(Ap + 8);
            a3 = *(const float4*)(Ap + 12);
            const float* Wp = W0 + (size_t)(k0 + 32) * Ndim;
            w00 = *(const float4*)(Wp);
            w01 = *(const float4*)(Wp + 4);
            w10 = *(const float4*)(Wp + Ndim);
            w11 = *(const float4*)(Wp + Ndim + 4);
        }

        // compute: 2 x k16 steps on buffer cur
        #pragma unroll
        for (int s = 0; s < 2; s++) {
            int kb = s * 8;
            unsigned afr[2][4], bfr[8][2];
            #pragma unroll
            for (int mt = 0; mt < 2; mt++) {
                int m0 = wm + mt * 16;
                afr[mt][0] = As[cur][kb + q    ][m0 + g    ];
                afr[mt][1] = As[cur][kb + q    ][m0 + g + 8];
                afr[mt][2] = As[cur][kb + q + 4][m0 + g    ];
                afr[mt][3] = As[cur][kb + q + 4][m0 + g + 8];
            }
            #pragma unroll
            for (int nt = 0; nt < 8; nt++) {
                int n0 = wn + nt * 8;
                bfr[nt][0] = Bs[cur][kb + q    ][n0 + g];
                bfr[nt][1] = Bs[cur][kb + q + 4][n0 + g];
            }
            #pragma unroll
            for (int mt = 0; mt < 2; mt++)
                #pragma unroll
                for (int nt = 0; nt < 8; nt++)
                    mma_f16(acc[mt][nt], afr[mt], bfr[nt]);
        }

        if (has_next) {
            int nb = cur ^ 1;
            As[nb][ak2 + 0][am] = f2h2(a0.x, a0.y);
            As[nb][ak2 + 1][am] = f2h2(a0.z, a0.w);
            As[nb][ak2 + 2][am] = f2h2(a1.x, a1.y);
            As[nb][ak2 + 3][am] = f2h2(a1.z, a1.w);
            As[nb][ak2 + 4][am] = f2h2(a2.x, a2.y);
            As[nb][ak2 + 5][am] = f2h2(a2.z, a2.w);
            As[nb][ak2 + 6][am] = f2h2(a3.x, a3.y);
            As[nb][ak2 + 7][am] = f2h2(a3.z, a3.w);
            unsigned* bp = &Bs[nb][bk2][bn0];
            bp[0] = f2h2(w00.x, w10.x); bp[1] = f2h2(w00.y, w10.y);
            bp[2] = f2h2(w00.z, w10.z); bp[3] = f2h2(w00.w, w10.w);
            bp[4] = f2h2(w01.x, w11.x); bp[5] = f2h2(w01.y, w11.y);
            bp[6] = f2h2(w01.z, w11.z); bp[7] = f2h2(w01.w, w11.w);
            __syncthreads();
            cur = nb;
        }
    }

    // Epilogue (same C-fragment layout as m16n8k8)
    #pragma unroll
    for (int mt = 0; mt < 2; mt++) {
        int r0 = bm + wm + mt * 16 + g;
        #pragma unroll
        for (int nt = 0; nt < 8; nt++) {
            int col = bn + wn + nt * 8 + q * 2;
            float bv0 = bias[col], bv1 = bias[col + 1];
            if (MODE == 0) {
                float* p0 = C + (size_t)r0 * Ndim + col;
                float* p1 = C + (size_t)(r0 + 8) * Ndim + col;
                p0[0] = acc[mt][nt][0] + bv0;
                p0[1] = acc[mt][nt][1] + bv1;
                p1[0] = acc[mt][nt][2] + bv0;
                p1[1] = acc[mt][nt][3] + bv1;
            } else {
                int h  = col >> 6;
                int dk = col & 63;
                int b0r = r0 >> 11, s0r = r0 & 2047;
                int b1r = (r0 + 8) >> 11, s1r = (r0 + 8) & 2047;
                float* p0 = C + (((size_t)(b0r * H_ + h) * S_ + s0r) * DK_ + dk);
                float* p1 = C + (((size_t)(b1r * H_ + h) * S_ + s1r) * DK_ + dk);
                p0[0] = acc[mt][nt][0] + bv0;
                p0[1] = acc[mt][nt][1] + bv1;
                p1[0] = acc[mt][nt][2] + bv0;
                p1[1] = acc[mt][nt][3] + bv1;
            }
        }
    }
}

// ---------------------------------------------------------------------------
// fp16 tensor-core causal flash attention (mma m16n8k16 + FFMA fast-exp).
// 256 threads / 8 warps. Q tile = 128 rows (m16 per warp), K/V tile = 64 keys.
// Q/K/P: half2 rows, u32 stride 40 (8 mod 32 -> conflict-free LDS).
// V: half rows, u32 stride 36 (144B -> conflict-free ldmatrix.trans).
// ---------------------------------------------------------------------------
#define KST2 40
#define VST2 36
#define PST2 40
#define FA_U32 (64*KST2 + 64*VST2 + 8*16*PST2)   // 9984 u32 = 39936 B

__global__ __launch_bounds__(256)
void flash_f16(const float* __restrict__ qh, const float* __restrict__ kh,
               const float* __restrict__ vh, float* __restrict__ out)
{
    extern __shared__ unsigned sm[];
    unsigned* Ksh = sm;                        // [64][KST2] half2(dk)
    unsigned* Vsh = sm + 64 * KST2;            // [64][VST2] halves(dk)
    int t = threadIdx.x;
    int wid = t >> 5, lane = t & 31;
    int g = lane >> 2, q = lane & 3;
    unsigned* Pw = sm + 64 * KST2 + 64 * VST2 + wid * 16 * PST2;  // [16][PST2]

    int bh = blockIdx.y;
    int b  = bh >> 4;
    int h  = bh & 15;
    int m0 = blockIdx.x * 128;
    int r0w = m0 + wid * 16;

    const float* qbase = qh + (size_t)bh * S_ * DK_;
    const float* kbase = kh + (size_t)bh * S_ * DK_;
    const float* vbase = vh + (size_t)bh * S_ * DK_;

    // ---- stage this warp's Q tile (16x64, scaled, fp16) ----
    #pragma unroll
    for (int i = 0; i < 8; ++i) {
        int idx = lane + 32 * i;               // 0..255 float4s
        int row = idx >> 4, c4 = idx & 15;
        float4 v = *(const float4*)(qbase + (size_t)(r0w + row) * DK_ + c4 * 4);
        Pw[row * PST2 + c4 * 2    ] = f2h2(v.x * 0.125f, v.y * 0.125f);
        Pw[row * PST2 + c4 * 2 + 1] = f2h2(v.z * 0.125f, v.w * 0.125f);
    }
    __syncwarp();

    unsigned aq[4][4];
    #pragma unroll
    for (int kk = 0; kk < 4; ++kk) {
        aq[kk][0] = Pw[ g      * PST2 + kk * 8 + q    ];
        aq[kk][1] = Pw[(g + 8) * PST2 + kk * 8 + q    ];
        aq[kk][2] = Pw[ g      * PST2 + kk * 8 + q + 4];
        aq[kk][3] = Pw[(g + 8) * PST2 + kk * 8 + q + 4];
    }

    float od[8][4];
    #pragma unroll
    for (int nt = 0; nt < 8; nt++)
        #pragma unroll
        for (int i = 0; i < 4; i++) od[nt][i] = 0.f;
    float mrow0 = -1e30f, mrow1 = -1e30f, lrow0 = 0.f, lrow1 = 0.f;

    uint32_t vl = smem_u32(Vsh) + (lane & 15) * (VST2 * 4);  // ldmatrix lane row ptr

    int nkb = 2 * (blockIdx.x + 1);            // causal: key blocks 0..nkb-1

    for (int kb = 0; kb < nkb; ++kb) {
        int jb = kb * 64;
        __syncthreads();                       // prior iteration consumers done
        // ---- cooperative K/V tile fill (64x64 each, fp16) ----
        #pragma unroll
        for (int i = 0; i < 4; ++i) {
            int idx = t + 256 * i;             // 0..1023 float4s
            int row = idx >> 4, c4 = idx & 15;
            float4 kv = *(const float4*)(kbase + (size_t)(jb + row) * DK_ + c4 * 4);
            Ksh[row * KST2 + c4 * 2    ] = f2h2(kv.x, kv.y);
            Ksh[row * KST2 + c4 * 2 + 1] = f2h2(kv.z, kv.w);
            float4 vv = *(const float4*)(vbase + (size_t)(jb + row) * DK_ + c4 * 4);
            Vsh[row * VST2 + c4 * 2    ] = f2h2(vv.x, vv.y);
            Vsh[row * VST2 + c4 * 2 + 1] = f2h2(vv.z, vv.w);
        }
        __syncthreads();

        if (jb > r0w + 15) continue;           // fully-future block for this warp

        // ---- S = Q @ K^T (16 x 64), fp32 accum ----
        float s[8][4];
        #pragma unroll
        for (int nt = 0; nt < 8; nt++)
            #pragma unroll
            for (int i = 0; i < 4; i++) s[nt][i] = 0.f;

        #pragma unroll
        for (int kk = 0; kk < 4; ++kk) {
            #pragma unroll
            for (int nt = 0; nt < 8; ++nt) {
                unsigned bfr[2];
                bfr[0] = Ksh[(nt * 8 + g) * KST2 + kk * 8 + q    ];
                bfr[1] = Ksh[(nt * 8 + g) * KST2 + kk * 8 + q + 4];
                mma_f16(s[nt], aq[kk], bfr);
            }
        }

        // ---- causal mask (diagonal blocks only) ----
        if (jb + 63 > r0w) {
            int row0 = r0w + g, row1 = r0w + g + 8;
            #pragma unroll
            for (int nt = 0; nt < 8; ++nt) {
                int j0 = jb + nt * 8 + 2 * q;
                if (j0     > row0) s[nt][0] = -1e30f;
                if (j0 + 1 > row0) s[nt][1] = -1e30f;
                if (j0     > row1) s[nt][2] = -1e30f;
                if (j0 + 1 > row1) s[nt][3] = -1e30f;
            }
        }

        // ---- online softmax ----
        float mx0 = s[0][0], mx1 = s[0][2];
        #pragma unroll
        for (int nt = 0; nt < 8; ++nt) {
            mx0 = fmaxf(mx0, fmaxf(s[nt][0], s[nt][1]));
            mx1 = fmaxf(mx1, fmaxf(s[nt][2], s[nt][3]));
        }
        mx0 = fmaxf(mx0, __shfl_xor_sync(0xffffffffu, mx0, 1));
        mx0 = fmaxf(mx0, __shfl_xor_sync(0xffffffffu, mx0, 2));
        mx1 = fmaxf(mx1, __shfl_xor_sync(0xffffffffu, mx1, 1));
        mx1 = fmaxf(mx1, __shfl_xor_sync(0xffffffffu, mx1, 2));

        float mn0 = fmaxf(mrow0, mx0);
        float mn1 = fmaxf(mrow1, mx1);
        float alpha0 = fexp(mrow0 - mn0);
        float alpha1 = fexp(mrow1 - mn1);
        mrow0 = mn0; mrow1 = mn1;

        float rs0 = 0.f, rs1 = 0.f;
        #pragma unroll
        for (int nt = 0; nt < 8; ++nt) {
            float p0 = fexp(s[nt][0] - mn0);
            float p1 = fexp(s[nt][1] - mn0);
            float p2 = fexp(s[nt][2] - mn1);
            float p3 = fexp(s[nt][3] - mn1);
            rs0 += p0 + p1;
            rs1 += p2 + p3;
            Pw[ g      * PST2 + nt * 4 + q] = f2h2(p0, p1);
            Pw[(g + 8) * PST2 + nt * 4 + q] = f2h2(p2, p3);
        }
        rs0 += __shfl_xor_sync(0xffffffffu, rs0, 1);
        rs0 += __shfl_xor_sync(0xffffffffu, rs0, 2);
        rs1 += __shfl_xor_sync(0xffffffffu, rs1, 1);
        rs1 += __shfl_xor_sync(0xffffffffu, rs1, 2);
        lrow0 = lrow0 * alpha0 + rs0;
        lrow1 = lrow1 * alpha1 + rs1;

        #pragma unroll
        for (int nt = 0; nt < 8; ++nt) {
            od[nt][0] *= alpha0; od[nt][1] *= alpha0;
            od[nt][2] *= alpha1; od[nt][3] *= alpha1;
        }
        __syncwarp();

        // ---- O += P @ V (16 x 64): A = P (smem), B = V via ldmatrix.trans ----
        #pragma unroll
        for (int kk = 0; kk < 4; ++kk) {
            unsigned ap[4];
            ap[0] = Pw[ g      * PST2 + kk * 8 + q    ];
            ap[1] = Pw[(g + 8) * PST2 + kk * 8 + q    ];
            ap[2] = Pw[ g      * PST2 + kk * 8 + q + 4];
            ap[3] = Pw[(g + 8) * PST2 + kk * 8 + q + 4];
            uint32_t vrow = vl + kk * 16 * (VST2 * 4);
            #pragma unroll
            for (int nt = 0; nt < 8; ++nt) {
                unsigned bfr[2];
                ldsm_x2_t(bfr[0], bfr[1], vrow + nt * 16);
                mma_f16(od[nt], ap, bfr);
            }
        }
        __syncwarp();   // Pw reads done before next-iteration P store
    }

    // ---- epilogue: normalize + write [B,S,D] ----
    float inv0 = 1.f / lrow0;
    float inv1 = 1.f / lrow1;
    int row0 = m0 + wid * 16 + g;
    int row1 = row0 + 8;
    float* o0 = out + ((size_t)b * S_ + row0) * D_ + h * DK_;
    float* o1 = out + ((size_t)b * S_ + row1) * D_ + h * DK_;
    #pragma unroll
    for (int nt = 0; nt < 8; ++nt) {
        int col = nt * 8 + 2 * q;
        float2 v0 = make_float2(od[nt][0] * inv0, od[nt][1] * inv0);
        float2 v1 = make_float2(od[nt][2] * inv1, od[nt][3] * inv1);
        *(float2*)(o0 + col) = v0;
        *(float2*)(o1 + col) = v1;
    }
}

// ---------------------------------------------------------------------------
// Launch: 3 projection GEMMs -> fp16 mma flash attention -> output GEMM
// ---------------------------------------------------------------------------
extern "C" void kernel_launch(void* const* d_in, const int* in_sizes, int n_in,
                              void* d_out, int out_size)
{
    const float* Q   = (const float*)d_in[0];
    const float* K   = (const float*)d_in[1];
    const float* V   = (const float*)d_in[2];
    const float* W_q = (const float*)d_in[3];
    const float* b_q = (const float*)d_in[4];
    const float* W_k = (const float*)d_in[5];
    const float* b_k = (const float*)d_in[6];
    const float* W_v = (const float*)d_in[7];
    const float* b_v = (const float*)d_in[8];
    const float* W_o = (const float*)d_in[9];
    const float* b_o = (const float*)d_in[10];
    float* out = (float*)d_out;

    float *gq, *gk, *gv, *ga;
    cudaGetSymbolAddress((void**)&gq, g_q);
    cudaGetSymbolAddress((void**)&gk, g_k);
    cudaGetSymbolAddress((void**)&gv, g_v);
    cudaGetSymbolAddress((void**)&ga, g_attn);

    cudaFuncSetAttribute(flash_f16, cudaFuncAttributeMaxDynamicSharedMemorySize,
                         FA_U32 * 4);

    dim3 gemm_grid(D_ / 128, M_ / 128);      // (8, 32)
    gemm_f16<1><<<gemm_grid, 256>>>(Q, W_q, b_q, gq, M_, D_, D_);
    gemm_f16<1><<<gemm_grid, 256>>>(K, W_k, b_k, gk, M_, D_, D_);
    gemm_f16<1><<<gemm_grid, 256>>>(V, W_v, b_v, gv, M_, D_, D_);

    flash_f16<<<dim3(S_ / 128, B_ * H_), 256, FA_U32 * 4>>>(gq, gk, gv, ga);

    gemm_f16<0><<<gemm_grid, 256>>>(ga, W_o, b_o, out, M_, D_, D_);
}

// round 10
// speedup vs baseline: 10.1216x; 1.3721x over previous
#include <cuda_runtime.h>
#include <cuda_fp16.h>
#include <cstdint>

// Problem constants
#define B_  2
#define S_  2048
#define D_  1024
#define H_  16
#define DK_ 64
#define M_  (B_*S_)   // 4096 rows

// Scratch (device globals: allocation-free)
__device__ float g_q[4194304];    // [B,H,S,DK]
__device__ float g_k[4194304];
__device__ float g_v[4194304];
__device__ float g_attn[4194304]; // [B,S,D]

// ---------------------------------------------------------------------------
// helpers
// ---------------------------------------------------------------------------
__device__ __forceinline__ unsigned f2h2(float lo, float hi) {
    __half2 h = __floats2half2_rn(lo, hi);
    return *(unsigned*)&h;
}

__device__ __forceinline__ uint32_t smem_u32(const void* p) {
    uint32_t a;
    asm("{ .reg .u64 t; cvta.to.shared.u64 t, %1; cvt.u32.u64 %0, t; }" : "=r"(a) : "l"(p));
    return a;
}

// fp16 mma, fp32 accumulate: D(16x8) += A(16x16) @ B(16x8)
__device__ __forceinline__ void mma_f16(float c[4], const unsigned a[4], unsigned b0, unsigned b1) {
    asm volatile(
        "mma.sync.aligned.m16n8k16.row.col.f32.f16.f16.f32 "
        "{%0,%1,%2,%3}, {%4,%5,%6,%7}, {%8,%9}, {%0,%1,%2,%3};"
        : "+f"(c[0]), "+f"(c[1]), "+f"(c[2]), "+f"(c[3])
        : "r"(a[0]), "r"(a[1]), "r"(a[2]), "r"(a[3]),
          "r"(b0), "r"(b1));
}

__device__ __forceinline__ void ldsm_x4(unsigned r[4], uint32_t addr) {
    asm volatile("ldmatrix.sync.aligned.m8n8.x4.shared.b16 {%0,%1,%2,%3}, [%4];"
                 : "=r"(r[0]), "=r"(r[1]), "=r"(r[2]), "=r"(r[3]) : "r"(addr));
}
__device__ __forceinline__ void ldsm_x4_t(unsigned r[4], uint32_t addr) {
    asm volatile("ldmatrix.sync.aligned.m8n8.x4.trans.shared.b16 {%0,%1,%2,%3}, [%4];"
                 : "=r"(r[0]), "=r"(r[1]), "=r"(r[2]), "=r"(r[3]) : "r"(addr));
}

// Fast e^x on the FMA/ALU pipes (no MUFU). Handles very negative x (mask) -> ~0.
__device__ __forceinline__ float fexp(float x) {
    float y = x * 1.44269504089f;          // log2(e)
    y = fmaxf(y, -126.0f);
    float z = __fadd_rn(y, 12582912.0f);   // rint via magic number
    int   iz = __float_as_int(z);
    float k = __fadd_rn(z, -12582912.0f);
    float f = y - k;                       // f in [-0.5, 0.5]
    float u = f * 0.69314718056f;
    float p = fmaf(u, fmaf(u, fmaf(u, fmaf(u, 0.041666668f, 0.16666667f), 0.5f), 1.0f), 1.0f);
    return __int_as_float(__float_as_int(p) + (iz << 23));  // p * 2^k
}

// ---------------------------------------------------------------------------
// fp16 GEMM body: C[4096,1024] = A[4096,1024] @ W[1024,1024] + bias
// BM=BN=128, BK=32, 256 threads / 8 warps (4x2), warp tile 32x64, m16n8k16.
// A smem: [2][128 rows][AST=20 u32]  (16 half2 data + pad; ldmatrix.x4, stride
//         20%32 -> 8-row phases hit all 32 banks).
// B smem: [2][32 k-rows][BST=68 u32] (64 half2 data + pad; ldmatrix.x4.trans,
//         68%32=4 -> conflict-free phases).
// MODE 0: row-major write. MODE 1: [B,H,S,DK] head layout write.
// ---------------------------------------------------------------------------
#define AST 20
#define BST 68

template<int MODE>
__device__ __forceinline__ void gemm_body(const float* __restrict__ A,
                                          const float* __restrict__ W,
                                          const float* __restrict__ bias,
                                          float* __restrict__ C)
{
    __shared__ unsigned As[2][128 * AST];
    __shared__ unsigned Bs[2][32 * BST];

    const int t    = threadIdx.x;
    const int lane = t & 31;
    const int warp = t >> 5;
    const int g    = lane >> 2;
    const int q    = lane & 3;

    const int bm = blockIdx.y * 128;
    const int bn = blockIdx.x * 128;
    const int wm = (warp & 3) * 32;
    const int wn = (warp >> 2) * 64;

    // fill mappings
    const int ar  = t >> 1;              // A rows handled: ar, with 4 float4 across k
    const int ac4 = (t & 1) * 4;         // base c4 (0 or 4)
    const int br_ = t >> 3;              // B k-row: 0..31
    const int bc4 = (t & 7) * 4;         // base c4 (x4 float4 span)

    float acc[2][8][4];
    #pragma unroll
    for (int mt = 0; mt < 2; mt++)
        #pragma unroll
        for (int nt = 0; nt < 8; nt++)
            #pragma unroll
            for (int i = 0; i < 4; i++) acc[mt][nt][i] = 0.f;

    const uint32_t Ab = smem_u32(As);
    const uint32_t Bb = smem_u32(Bs);

    // per-lane ldmatrix address components
    const uint32_t a_lrow = (uint32_t)(lane & 15);
    const uint32_t a_lcol = (lane & 16) ? 16u : 0u;
    const uint32_t b_lrow = (uint32_t)((lane & 7) + ((lane & 8) ? 8 : 0));
    const uint32_t b_lcol = (lane & 16) ? 16u : 0u;

    float4 a_st[4], b_st[4];

    auto load_regs = [&](int k0) {
        #pragma unroll
        for (int i = 0; i < 4; ++i)
            a_st[i] = *(const float4*)(A + (size_t)(bm + ar) * 1024 + k0 + ac4 * 4 + i * 8 - i * 8 + (i & 1) * 16 + (i >> 1) * 0);   // placeholder
    };
    (void)load_regs;

    // --- explicit fill: global -> regs -> smem (converted) ---
    auto fill = [&](int k0, int buf) {
        // A: 1024 float4 total; thread: rows spread, 4 loads
        #pragma unroll
        for (int i = 0; i < 4; ++i) {
            int idx = t + 256 * i;           // 0..1023
            int row = idx >> 3;              // 0..127
            int c4  = idx & 7;               // 0..7
            float4 v = *(const float4*)(A + (size_t)(bm + row) * 1024 + k0 + c4 * 4);
            uint2 u = make_uint2(f2h2(v.x, v.y), f2h2(v.z, v.w));
            *(uint2*)&As[buf][row * AST + c4 * 2] = u;
        }
        // B: 1024 float4 total
        #pragma unroll
        for (int i = 0; i < 4; ++i) {
            int idx = t + 256 * i;
            int row = idx >> 5;              // k: 0..31
            int c4  = idx & 31;              // 0..31
            float4 v = *(const float4*)(W + (size_t)(k0 + row) * 1024 + bn + c4 * 4);
            uint2 u = make_uint2(f2h2(v.x, v.y), f2h2(v.z, v.w));
            *(uint2*)&Bs[buf][row * BST + c4 * 2] = u;
        }
    };

    fill(0, 0);
    __syncthreads();

    for (int k0 = 0; k0 < 1024; k0 += 32) {
        int buf = (k0 >> 5) & 1;
        bool has_next = (k0 + 32) < 1024;
        if (has_next) {
            // prefetch next chunk into regs
            #pragma unroll
            for (int i = 0; i < 4; ++i) {
                int idx = t + 256 * i;
                int row = idx >> 3, c4 = idx & 7;
                a_st[i] = *(const float4*)(A + (size_t)(bm + row) * 1024 + (k0 + 32) + c4 * 4);
            }
            #pragma unroll
            for (int i = 0; i < 4; ++i) {
                int idx = t + 256 * i;
                int row = idx >> 5, c4 = idx & 31;
                b_st[i] = *(const float4*)(W + (size_t)(k0 + 32 + row) * 1024 + bn + c4 * 4);
            }
        }

        // compute on buf: 2 x k16 steps
        #pragma unroll
        for (int s = 0; s < 2; ++s) {
            unsigned afr[2][4];
            #pragma unroll
            for (int mt = 0; mt < 2; ++mt)
                ldsm_x4(afr[mt], Ab + (uint32_t)buf * (128 * AST * 4)
                                   + (uint32_t)(wm + mt * 16 + a_lrow) * (AST * 4)
                                   + (uint32_t)s * 32 + a_lcol);
            unsigned bfr[4][4];
            #pragma unroll
            for (int np = 0; np < 4; ++np)
                ldsm_x4_t(bfr[np], Bb + (uint32_t)buf * (32 * BST * 4)
                                     + ((uint32_t)s * 16 + b_lrow) * (BST * 4)
                                     + (uint32_t)(wn + np * 16) * 2 + b_lcol);
            #pragma unroll
            for (int mt = 0; mt < 2; ++mt)
                #pragma unroll
                for (int np = 0; np < 4; ++np) {
                    mma_f16(acc[mt][2 * np    ], afr[mt], bfr[np][0], bfr[np][1]);
                    mma_f16(acc[mt][2 * np + 1], afr[mt], bfr[np][2], bfr[np][3]);
                }
        }

        if (has_next) {
            __syncthreads();
            int nb = buf ^ 1;
            #pragma unroll
            for (int i = 0; i < 4; ++i) {
                int idx = t + 256 * i;
                int row = idx >> 3, c4 = idx & 7;
                uint2 u = make_uint2(f2h2(a_st[i].x, a_st[i].y), f2h2(a_st[i].z, a_st[i].w));
                *(uint2*)&As[nb][row * AST + c4 * 2] = u;
            }
            #pragma unroll
            for (int i = 0; i < 4; ++i) {
                int idx = t + 256 * i;
                int row = idx >> 5, c4 = idx & 31;
                uint2 u = make_uint2(f2h2(b_st[i].x, b_st[i].y), f2h2(b_st[i].z, b_st[i].w));
                *(uint2*)&Bs[nb][row * BST + c4 * 2] = u;
            }
            __syncthreads();
        }
    }

    // Epilogue
    #pragma unroll
    for (int mt = 0; mt < 2; mt++) {
        int r0 = bm + wm + mt * 16 + g;
        #pragma unroll
        for (int nt = 0; nt < 8; nt++) {
            int col = bn + wn + nt * 8 + q * 2;
            float bv0 = bias[col], bv1 = bias[col + 1];
            if (MODE == 0) {
                float* p0 = C + (size_t)r0 * 1024 + col;
                float* p1 = C + (size_t)(r0 + 8) * 1024 + col;
                p0[0] = acc[mt][nt][0] + bv0;
                p0[1] = acc[mt][nt][1] + bv1;
                p1[0] = acc[mt][nt][2] + bv0;
                p1[1] = acc[mt][nt][3] + bv1;
            } else {
                int h  = col >> 6;
                int dk = col & 63;
                int b0r = r0 >> 11, s0r = r0 & 2047;
                int b1r = (r0 + 8) >> 11, s1r = (r0 + 8) & 2047;
                float* p0 = C + (((size_t)(b0r * H_ + h) * S_ + s0r) * DK_ + dk);
                float* p1 = C + (((size_t)(b1r * H_ + h) * S_ + s1r) * DK_ + dk);
                p0[0] = acc[mt][nt][0] + bv0;
                p0[1] = acc[mt][nt][1] + bv1;
                p1[0] = acc[mt][nt][2] + bv0;
                p1[1] = acc[mt][nt][3] + bv1;
            }
        }
    }
}

// Fused Q/K/V projection: blockIdx.z selects which projection.
__global__ __launch_bounds__(256, 2)
void qkv_gemm(const float* __restrict__ Q, const float* __restrict__ K,
              const float* __restrict__ V,
              const float* __restrict__ Wq, const float* __restrict__ Wk,
              const float* __restrict__ Wv,
              const float* __restrict__ bq, const float* __restrict__ bk,
              const float* __restrict__ bv,
              float* __restrict__ Cq, float* __restrict__ Ck, float* __restrict__ Cv)
{
    int z = blockIdx.z;
    const float* A = (z == 0) ? Q : (z == 1) ? K : V;
    const float* W = (z == 0) ? Wq : (z == 1) ? Wk : Wv;
    const float* b = (z == 0) ? bq : (z == 1) ? bk : bv;
    float*       C = (z == 0) ? Cq : (z == 1) ? Ck : Cv;
    gemm_body<1>(A, W, b, C);
}

__global__ __launch_bounds__(256, 2)
void out_gemm(const float* __restrict__ A, const float* __restrict__ W,
              const float* __restrict__ b, float* __restrict__ C)
{
    gemm_body<0>(A, W, b, C);
}

// ---------------------------------------------------------------------------
// fp16 tensor-core causal flash attention, v2:
//  - K fragments via ldmatrix.x4 (non-trans), V via ldmatrix.x4.trans
//  - P kept in registers (C-frag -> A-frag repack), no smem round-trip
//  - diagonal blocks skip fully-masked 16-key pairs (nplim)
// 256 threads / 8 warps, Q tile 128 (m16/warp), K/V tile 64.
// smem strides 36 u32 (stride%32=4 -> conflict-free ldmatrix phases).
// ---------------------------------------------------------------------------
#define FST 36
// smem: K [64][36], V [64][36], Qw 8 x [16][36]
#define FLASH_U32 (64*FST + 64*FST + 8*16*FST)

__global__ __launch_bounds__(256, 2)
void flash_f16(const float* __restrict__ qh, const float* __restrict__ kh,
               const float* __restrict__ vh, float* __restrict__ out)
{
    __shared__ unsigned sm[FLASH_U32];
    unsigned* Ksh = sm;
    unsigned* Vsh = sm + 64 * FST;
    int t = threadIdx.x;
    int wid = t >> 5, lane = t & 31;
    int g = lane >> 2, q = lane & 3;
    unsigned* Qw = sm + 128 * FST + wid * 16 * FST;

    int bh = blockIdx.y;
    int b  = bh >> 4;
    int h  = bh & 15;
    int m0 = blockIdx.x * 128;
    int r0w = m0 + wid * 16;

    const float* qbase = qh + (size_t)bh * S_ * DK_;
    const float* kbase = kh + (size_t)bh * S_ * DK_;
    const float* vbase = vh + (size_t)bh * S_ * DK_;

    // ---- stage this warp's Q tile (16x64, scaled, fp16) ----
    #pragma unroll
    for (int i = 0; i < 8; ++i) {
        int idx = lane + 32 * i;               // 0..255 float4s
        int row = idx >> 4, c4 = idx & 15;
        float4 v = *(const float4*)(qbase + (size_t)(r0w + row) * DK_ + c4 * 4);
        Qw[row * FST + c4 * 2    ] = f2h2(v.x * 0.125f, v.y * 0.125f);
        Qw[row * FST + c4 * 2 + 1] = f2h2(v.z * 0.125f, v.w * 0.125f);
    }
    __syncwarp();

    const uint32_t Kb = smem_u32(Ksh);
    const uint32_t Vb = smem_u32(Vsh);
    const uint32_t Qb = smem_u32(Qw);

    // Q A-frags via ldmatrix.x4 (one per k16 chunk)
    unsigned aq[4][4];
    {
        uint32_t qaddr = Qb + (uint32_t)(lane & 15) * (FST * 4) + ((lane & 16) ? 16u : 0u);
        #pragma unroll
        for (int kk = 0; kk < 4; ++kk)
            ldsm_x4(aq[kk], qaddr + kk * 32);
    }

    // ldmatrix lane address components
    const uint32_t k_lrow = (uint32_t)((lane & 7) + ((lane & 16) ? 8 : 0)) * (FST * 4)
                          + ((lane & 8) ? 16u : 0u);
    const uint32_t v_lrow = (uint32_t)((lane & 7) + ((lane & 8) ? 8 : 0)) * (FST * 4)
                          + ((lane & 16) ? 16u : 0u);

    float od[8][4];
    #pragma unroll
    for (int nt = 0; nt < 8; nt++)
        #pragma unroll
        for (int i = 0; i < 4; i++) od[nt][i] = 0.f;
    float mrow0 = -1e30f, mrow1 = -1e30f, lrow0 = 0.f, lrow1 = 0.f;

    int nkb = 2 * (blockIdx.x + 1);            // causal: key blocks 0..nkb-1

    for (int kb = 0; kb < nkb; ++kb) {
        int jb = kb * 64;
        __syncthreads();                       // prior iteration consumers done
        // ---- cooperative K/V tile fill (64x64 each, fp16) ----
        #pragma unroll
        for (int i = 0; i < 4; ++i) {
            int idx = t + 256 * i;             // 0..1023 float4s
            int row = idx >> 4, c4 = idx & 15;
            float4 kv = *(const float4*)(kbase + (size_t)(jb + row) * DK_ + c4 * 4);
            Ksh[row * FST + c4 * 2    ] = f2h2(kv.x, kv.y);
            Ksh[row * FST + c4 * 2 + 1] = f2h2(kv.z, kv.w);
            float4 vv = *(const float4*)(vbase + (size_t)(jb + row) * DK_ + c4 * 4);
            Vsh[row * FST + c4 * 2    ] = f2h2(vv.x, vv.y);
            Vsh[row * FST + c4 * 2 + 1] = f2h2(vv.z, vv.w);
        }
        __syncthreads();

        if (jb > r0w + 15) continue;           // fully-future block for this warp

        // valid 16-key pairs for this warp (uniform across warp)
        int nplim = ((r0w + 15 - jb) >> 4) + 1;
        if (nplim > 4) nplim = 4;
        int ntlim = 2 * nplim;

        // ---- S = Q @ K^T (16 x up-to-64), fp32 accum ----
        float s[8][4];
        #pragma unroll
        for (int nt = 0; nt < 8; nt++)
            #pragma unroll
            for (int i = 0; i < 4; i++) s[nt][i] = 0.f;

        #pragma unroll
        for (int kk = 0; kk < 4; ++kk) {
            #pragma unroll
            for (int np = 0; np < 4; ++np) {
                if (np < nplim) {
                    unsigned bfr[4];
                    ldsm_x4(bfr, Kb + (uint32_t)np * (16 * FST * 4) + (uint32_t)kk * 32 + k_lrow);
                    mma_f16(s[2 * np    ], aq[kk], bfr[0], bfr[1]);
                    mma_f16(s[2 * np + 1], aq[kk], bfr[2], bfr[3]);
                }
            }
        }

        // ---- causal mask (diagonal region only) ----
        if (jb + 63 > r0w) {
            int row0 = r0w + g, row1 = r0w + g + 8;
            #pragma unroll
            for (int nt = 0; nt < 8; ++nt) {
                if (nt < ntlim) {
                    int j0 = jb + nt * 8 + 2 * q;
                    if (j0     > row0) s[nt][0] = -1e30f;
                    if (j0 + 1 > row0) s[nt][1] = -1e30f;
                    if (j0     > row1) s[nt][2] = -1e30f;
                    if (j0 + 1 > row1) s[nt][3] = -1e30f;
                }
            }
        }

        // ---- online softmax ----
        float mx0 = -1e30f, mx1 = -1e30f;
        #pragma unroll
        for (int nt = 0; nt < 8; ++nt) {
            if (nt < ntlim) {
                mx0 = fmaxf(mx0, fmaxf(s[nt][0], s[nt][1]));
                mx1 = fmaxf(mx1, fmaxf(s[nt][2], s[nt][3]));
            }
        }
        mx0 = fmaxf(mx0, __shfl_xor_sync(0xffffffffu, mx0, 1));
        mx0 = fmaxf(mx0, __shfl_xor_sync(0xffffffffu, mx0, 2));
        mx1 = fmaxf(mx1, __shfl_xor_sync(0xffffffffu, mx1, 1));
        mx1 = fmaxf(mx1, __shfl_xor_sync(0xffffffffu, mx1, 2));

        float mn0 = fmaxf(mrow0, mx0);
        float mn1 = fmaxf(mrow1, mx1);
        float alpha0 = fexp(mrow0 - mn0);
        float alpha1 = fexp(mrow1 - mn1);
        mrow0 = mn0; mrow1 = mn1;

        unsigned ph0[8], ph1[8];
        float rs0 = 0.f, rs1 = 0.f;
        #pragma unroll
        for (int nt = 0; nt < 8; ++nt) {
            if (nt < ntlim) {
                float p0 = fexp(s[nt][0] - mn0);
                float p1 = fexp(s[nt][1] - mn0);
                float p2 = fexp(s[nt][2] - mn1);
                float p3 = fexp(s[nt][3] - mn1);
                rs0 += p0 + p1;
                rs1 += p2 + p3;
                ph0[nt] = f2h2(p0, p1);        // A-frag a0/a2 source (row g)
                ph1[nt] = f2h2(p2, p3);        // A-frag a1/a3 source (row g+8)
            }
        }
        rs0 += __shfl_xor_sync(0xffffffffu, rs0, 1);
        rs0 += __shfl_xor_sync(0xffffffffu, rs0, 2);
        rs1 += __shfl_xor_sync(0xffffffffu, rs1, 1);
        rs1 += __shfl_xor_sync(0xffffffffu, rs1, 2);
        lrow0 = lrow0 * alpha0 + rs0;
        lrow1 = lrow1 * alpha1 + rs1;

        #pragma unroll
        for (int nt = 0; nt < 8; ++nt) {
            od[nt][0] *= alpha0; od[nt][1] *= alpha0;
            od[nt][2] *= alpha1; od[nt][3] *= alpha1;
        }

        // ---- O += P @ V : P A-frags direct from registers, V via x4.trans ----
        #pragma unroll
        for (int kk = 0; kk < 4; ++kk) {       // key 16-chunks
            if (kk < nplim) {
                unsigned ap[4];
                ap[0] = ph0[2 * kk];
                ap[1] = ph1[2 * kk];
                ap[2] = ph0[2 * kk + 1];
                ap[3] = ph1[2 * kk + 1];
                #pragma unroll
                for (int np = 0; np < 4; ++np) {   // dk 16-chunks
                    unsigned bfr[4];
                    ldsm_x4_t(bfr, Vb + (uint32_t)kk * (16 * FST * 4) + (uint32_t)np * 32 + v_lrow);
                    mma_f16(od[2 * np    ], ap, bfr[0], bfr[1]);
                    mma_f16(od[2 * np + 1], ap, bfr[2], bfr[3]);
                }
            }
        }
    }

    // ---- epilogue: normalize + write [B,S,D] ----
    float inv0 = 1.f / lrow0;
    float inv1 = 1.f / lrow1;
    int row0 = m0 + wid * 16 + g;
    int row1 = row0 + 8;
    float* o0 = out + ((size_t)b * S_ + row0) * D_ + h * DK_;
    float* o1 = out + ((size_t)b * S_ + row1) * D_ + h * DK_;
    #pragma unroll
    for (int nt = 0; nt < 8; ++nt) {
        int col = nt * 8 + 2 * q;
        float2 v0 = make_float2(od[nt][0] * inv0, od[nt][1] * inv0);
        float2 v1 = make_float2(od[nt][2] * inv1, od[nt][3] * inv1);
        *(float2*)(o0 + col) = v0;
        *(float2*)(o1 + col) = v1;
    }
}

// ---------------------------------------------------------------------------
// Launch: fused QKV projection -> flash attention -> output GEMM
// ---------------------------------------------------------------------------
extern "C" void kernel_launch(void* const* d_in, const int* in_sizes, int n_in,
                              void* d_out, int out_size)
{
    const float* Q   = (const float*)d_in[0];
    const float* K   = (const float*)d_in[1];
    const float* V   = (const float*)d_in[2];
    const float* W_q = (const float*)d_in[3];
    const float* b_q = (const float*)d_in[4];
    const float* W_k = (const float*)d_in[5];
    const float* b_k = (const float*)d_in[6];
    const float* W_v = (const float*)d_in[7];
    const float* b_v = (const float*)d_in[8];
    const float* W_o = (const float*)d_in[9];
    const float* b_o = (const float*)d_in[10];
    float* out = (float*)d_out;

    float *gq, *gk, *gv, *ga;
    cudaGetSymbolAddress((void**)&gq, g_q);
    cudaGetSymbolAddress((void**)&gk, g_k);
    cudaGetSymbolAddress((void**)&gv, g_v);
    cudaGetSymbolAddress((void**)&ga, g_attn);

    qkv_gemm<<<dim3(8, 32, 3), 256>>>(Q, K, V, W_q, W_k, W_v,
                                      b_q, b_k, b_v, gq, gk, gv);

    flash_f16<<<dim3(S_ / 128, B_ * H_), 256>>>(gq, gk, gv, ga);

    out_gemm<<<dim3(8, 32), 256>>>(ga, W_o, b_o, out);
}